// round 16
// baseline (speedup 1.0000x reference)
#include <cuda_runtime.h>
#include <cstdint>

// AdaptiveEdgeSparsifier: per-row (4096) exact k-th-largest threshold, then
// out = (adj >= kth) ? adj : 0.
//
// R15: single-pass classify-and-store. The threshold always lies inside the
// u-window (raw bits [UA,UB) <=> f in (-0.66015625, -0.3984375], +-6.3 sigma
// around the per-row 0.30-quantile), so:
//   above window  -> certainly kept   -> store f immediately
//   at/below low  -> certainly zeroed -> store 0 immediately
//   in-window     -> store provisional 0; collect (value,idx) in smem
// After the select (186-bin histogram -> bucket -> m-th largest over UNIQUE
// value||idx packed keys), only the collected in-window winners (~100-300
// scattered floats) are overwritten. The row is read ONCE and written ONCE:
// no TMA, no smem row, no second pass. Collect uses ballot-aggregated
// appends (1 ATOMS per warp-element). Exact 32-bit descent over cached
// global reads + full rewrite remains the never-taken fallback.

#define N_COLS    4096
#define TPB       256
#define MAXCOLL   1024
#define MAXB      32

#define UA        0xBECC0000u
#define UB        0xBF290000u
#define BIN_SHIFT 15
#define HI_STRICT (-0.3984375f)   /* f > HI_STRICT <=> strictly above window */

__device__ __forceinline__ unsigned f2key(float f) {
    unsigned u = __float_as_uint(f);
    return u ^ ((unsigned)((int)u >> 31) | 0x80000000u);
}
__device__ __forceinline__ float key2f(unsigned k) {
    unsigned u = (k & 0x80000000u) ? (k ^ 0x80000000u) : ~k;
    return __uint_as_float(u);
}

__device__ __forceinline__ unsigned long long warp_max_u64(unsigned long long v) {
#pragma unroll
    for (int d = 16; d > 0; d >>= 1) {
        unsigned long long o = __shfl_xor_sync(0xFFFFFFFFu, v, d);
        if (o > v) v = o;
    }
    return v;
}

__global__ void __launch_bounds__(TPB, 8)
topk_sparsify_kernel(const float4* __restrict__ in,
                     float4* __restrict__ out,
                     int kth)
{
    __shared__ unsigned            s_val[MAXCOLL];      // in-window raw bits
    __shared__ unsigned short      s_idx[MAXCOLL];      // their column index
    __shared__ int                 s_hist[192];
    __shared__ unsigned long long  s_bucket[MAXB];
    __shared__ int                 s_part[2][TPB / 32];
    __shared__ int                 s_chi, s_cur, s_cur2, s_j, s_m, s_nb, s_fb;
    __shared__ float               s_ft;

    const int tid  = threadIdx.x;
    const int lane = tid & 31;
    const size_t row_f4 = (size_t)blockIdx.x * (N_COLS / 4);
    const float4* gp = in  + row_f4 + tid;
    float4*       qp = out + row_f4 + tid;

    if (tid < 192) s_hist[tid] = 0;
    if (tid == 0) { s_chi = 0; s_cur = 0; s_cur2 = 0; s_fb = 0; }
    __syncthreads();

    // ---- Pass A: stream once; classify, store, collect in-window ----
    int chi = 0;
#pragma unroll
    for (int i = 0; i < 4; ++i) {
        float4 v = __ldg(&gp[i * TPB]);
        float fv[4] = {v.x, v.y, v.z, v.w};
        float ov[4];
#pragma unroll
        for (int c = 0; c < 4; ++c) {
            float f = fv[c];
            bool above = f > HI_STRICT;               // certainly kept
            chi += above ? 1 : 0;
            ov[c] = above ? f : 0.0f;                 // provisional for window
            unsigned u = __float_as_uint(f);
            bool inwin = (u - UA) < (UB - UA);        // negative-window test
            unsigned mb = __ballot_sync(0xFFFFFFFFu, inwin);
            if (mb) {                                 // warp-uniform
                int leader = __ffs(mb) - 1;
                int base = 0;
                if (lane == leader) base = atomicAdd(&s_cur, __popc(mb));
                base = __shfl_sync(0xFFFFFFFFu, base, leader);
                if (inwin) {
                    int slot = base + __popc(mb & ((1u << lane) - 1));
                    if (slot < MAXCOLL) {
                        s_val[slot] = u;
                        s_idx[slot] = (unsigned short)((((i * TPB) + tid) << 2) | c);
                    }
                }
            }
        }
        float4 o; o.x = ov[0]; o.y = ov[1]; o.z = ov[2]; o.w = ov[3];
        qp[i * TPB] = o;
    }
    chi = __reduce_add_sync(0xFFFFFFFFu, chi);
    if (lane == 0) atomicAdd(&s_chi, chi);
    __syncthreads();

    const int ncoll = s_cur;
    const int chitot = s_chi;
    const int nscan = (ncoll < MAXCOLL) ? ncoll : MAXCOLL;
    if (tid == 0 && ncoll > MAXCOLL) s_fb = 1;        // overflow -> fallback

    // ---- Pass B: histogram collected (~371) into 186 key-domain bins ----
    for (int i = tid; i < nscan; i += TPB) {
        unsigned u = s_val[i];
        atomicAdd(&s_hist[(UB - 1u - u) >> BIN_SHIFT], 1);
    }
    __syncthreads();

    // ---- Pass C: warp-0 suffix scan; bucket j* with cum(j*)>=k>cum(j*+1) ----
    if (tid < 32) {
        int h[6];
        int lt = 0;
#pragma unroll
        for (int r = 0; r < 6; ++r) { h[r] = s_hist[lane * 6 + r]; lt += h[r]; }
        int x = lt;                                   // suffix sum over lanes
#pragma unroll
        for (int d = 1; d < 32; d <<= 1) {
            int y = __shfl_down_sync(0xFFFFFFFFu, x, d);
            if (lane + d < 32) x += y;
        }
        const int cumbase = chitot + x;               // count(bin >= 6*lane)
        int cand = -1, candcum = 0, candh = 0, pre = 0;
#pragma unroll
        for (int r = 0; r < 6; ++r) {
            int j   = lane * 6 + r;
            int cum = cumbase - pre;                  // count(bin >= j)
            if (cum >= kth) { cand = j; candcum = cum; candh = h[r]; }
            pre += h[r];
        }
        int jstar = __reduce_max_sync(0xFFFFFFFFu, cand);
        if (cand == jstar && jstar >= 0) {            // unique owner lane
            s_j = jstar;
            s_m = kth - (candcum - candh);            // 1 <= m <= bucket size
            s_nb = candh;
            if (candh > MAXB) s_fb = 1;
        }
        if (lane == 0 && (jstar < 0 || chitot >= kth)) s_fb = 1;
    }
    __syncthreads();

    if (!s_fb) {
        // ---- Pass D: gather bucket members as UNIQUE packed keys ----
        // key = (~u) << 16 | idx : monotone in value, idx tiebreak, unique.
        const unsigned ubhi = UB - 1u - ((unsigned)s_j << BIN_SHIFT);
        for (int i = tid; i < nscan; i += TPB) {
            unsigned u = s_val[i];
            if ((ubhi - u) < (1u << BIN_SHIFT)) {
                int pos = atomicAdd(&s_cur2, 1);
                s_bucket[pos] = ((unsigned long long)(~u) << 16) | s_idx[i];
            }
        }
        __syncthreads();

        // warp 0: m-th largest among <=32 unique keys
        if (tid < 32) {
            const int nb = s_nb, m = s_m;
            unsigned long long kv = (lane < nb) ? s_bucket[lane] : 0ull;
            for (int i = 1; i < m; ++i) {
                unsigned long long mx = warp_max_u64(kv);
                kv = (kv == mx) ? 0ull : kv;          // unique: removes one
            }
            unsigned long long sel = warp_max_u64(kv);
            if (lane == 0)
                s_ft = __uint_as_float(~(unsigned)(sel >> 16));
        }
        __syncthreads();
        const float ft = s_ft;

        // ---- Pass D': overwrite kept in-window elements (scattered) ----
        float* orow = (float*)(out + row_f4);
        for (int i = tid; i < nscan; i += TPB) {
            float f = __uint_as_float(s_val[i]);
            if (f >= ft) orow[s_idx[i]] = f;
        }
    } else {
        // ---- exact fallback: descent over cached global row, full rewrite ----
        unsigned result = 0u;
#pragma unroll 1
        for (int bit = 31; bit >= 0; --bit) {
            const unsigned t = result | (1u << bit);
            int c = 0;
#pragma unroll
            for (int i = 0; i < 4; ++i) {
                float4 v = __ldg(&gp[i * TPB]);
                c += (f2key(v.x) >= t) ? 1 : 0;
                c += (f2key(v.y) >= t) ? 1 : 0;
                c += (f2key(v.z) >= t) ? 1 : 0;
                c += (f2key(v.w) >= t) ? 1 : 0;
            }
            c = __reduce_add_sync(0xFFFFFFFFu, c);
            if (lane == 0) s_part[bit & 1][tid >> 5] = c;
            __syncthreads();
            int tot = 0;
#pragma unroll
            for (int w = 0; w < TPB / 32; ++w) tot += s_part[bit & 1][w];
            if (tot >= kth) { result = t; if (tot == kth) break; }   // uniform
        }
        const float ft = key2f(result);
#pragma unroll
        for (int i = 0; i < 4; ++i) {
            float4 v = __ldg(&gp[i * TPB]);
            v.x = (v.x >= ft) ? v.x : 0.0f;
            v.y = (v.y >= ft) ? v.y : 0.0f;
            v.z = (v.z >= ft) ? v.z : 0.0f;
            v.w = (v.w >= ft) ? v.w : 0.0f;
            qp[i * TPB] = v;
        }
    }
}

extern "C" void kernel_launch(void* const* d_in, const int* in_sizes, int n_in,
                              void* d_out, int out_size)
{
    const float4* in  = (const float4*)d_in[0];
    float4*       out = (float4*)d_out;

    const int rows = in_sizes[0] / N_COLS;        // 8 * 4096 = 32768

    int k = (int)((double)N_COLS * (1.0 - 0.3));  // 2867, matches Python int()
    if (k < 1) k = 1;

    topk_sparsify_kernel<<<rows, TPB>>>(in, out, k);
}

// round 17
// speedup vs baseline: 1.3141x; 1.3141x over previous
#include <cuda_runtime.h>
#include <cstdint>

// AdaptiveEdgeSparsifier: per-row (4096) exact k-th-largest threshold, then
// out = (adj >= kth) ? adj : 0.
//
// R16 = R15's memory shape + R13's collect mechanism.
// Single pass: LDG.128 the row once, immediately STG.128 the classified
// output (above-window -> f, else provisional 0), and append the ~371
// in-window (value,idx) pairs to smem with a BRANCH-FREE per-lane predicated
// asm sequence (setp / @p atom.shared.add / @q st.shared) — no ballots, no
// divergent regions (R15's ballot choreography was the regression). Select:
// 186-bin key histogram -> bucket -> m-th largest over unique value||idx
// packed keys; then overwrite only the kept in-window elements (scattered
// 4B stores, ordered behind pass A by __syncthreads). Exact 32-bit descent
// + full rewrite stays as the never-taken fallback.

#define N_COLS    4096
#define TPB       256
#define MAXCOLL   1024
#define MAXB      32

// u-domain window (raw bits of negative floats): u in [UA,UB) <=> f in
// (-0.66015625, -0.3984375], +-6.3 sigma around the per-row 0.30-quantile
// (~ -0.5237 +- 0.0206) of 4096 N(0,1) samples. For negatives key = ~u;
// bin = (UB-1-u) >> 15 is monotone increasing in f. 186 bins.
#define UA        0xBECC0000u
#define UB        0xBF290000u
#define BIN_SHIFT 15
#define HI_STRICT (-0.3984375f)   /* f > HI_STRICT <=> strictly above window */

__device__ __forceinline__ unsigned f2key(float f) {
    unsigned u = __float_as_uint(f);
    return u ^ ((unsigned)((int)u >> 31) | 0x80000000u);
}
__device__ __forceinline__ float key2f(unsigned k) {
    unsigned u = (k & 0x80000000u) ? (k ^ 0x80000000u) : ~k;
    return __uint_as_float(u);
}

__device__ __forceinline__ unsigned long long warp_max_u64(unsigned long long v) {
#pragma unroll
    for (int d = 16; d > 0; d >>= 1) {
        unsigned long long o = __shfl_xor_sync(0xFFFFFFFFu, v, d);
        if (o > v) v = o;
    }
    return v;
}

// Branch-free classify+collect for one element: returns output value,
// appends (raw bits, idx) to smem if in-window (capacity-guarded).
__device__ __forceinline__ float classify_elem(float f, unsigned idx, int& chi,
                                               unsigned curaddr,
                                               unsigned valbase,
                                               unsigned idxbase)
{
    bool above = f > HI_STRICT;
    chi += above ? 1 : 0;
    unsigned u = __float_as_uint(f);
    asm volatile(
        "{ .reg .pred p, q; .reg .u32 d, t, a;\n"
        "  add.u32 d, %0, %1;\n"                    // d = u - UA
        "  setp.lt.u32 p, d, %2;\n"                 // in window?
        "  @p atom.shared.add.u32 t, [%3], 1;\n"
        "  setp.lt.and.u32 q, t, %6, p;\n"          // slot < cap
        "  @q mad.lo.u32 a, t, 4, %4;\n"
        "  @q st.shared.b32 [a], %0;\n"
        "  @q mad.lo.u32 a, t, 2, %5;\n"
        "  @q st.shared.b16 [a], %7;\n}"
        :: "r"(u), "r"(0u - UA), "r"(UB - UA),
           "r"(curaddr), "r"(valbase), "r"(idxbase),
           "r"((unsigned)MAXCOLL), "r"(idx)
        : "memory");
    return above ? f : 0.0f;
}

__global__ void __launch_bounds__(TPB, 8)
topk_sparsify_kernel(const float4* __restrict__ in,
                     float4* __restrict__ out,
                     int kth)
{
    __shared__ unsigned            s_val[MAXCOLL];      // in-window raw bits
    __shared__ unsigned short      s_idx[MAXCOLL];      // their column index
    __shared__ int                 s_hist[192];
    __shared__ unsigned long long  s_bucket[MAXB];
    __shared__ int                 s_part[2][TPB / 32];
    __shared__ int                 s_chi, s_cur, s_cur2, s_j, s_m, s_nb, s_fb;
    __shared__ float               s_ft;

    const int tid  = threadIdx.x;
    const int lane = tid & 31;
    const size_t row_f4 = (size_t)blockIdx.x * (N_COLS / 4);
    const float4* gp = in  + row_f4 + tid;
    float4*       qp = out + row_f4 + tid;

    if (tid < 192) s_hist[tid] = 0;
    if (tid == 0) { s_chi = 0; s_cur = 0; s_cur2 = 0; s_fb = 0; }
    __syncthreads();

    // ---- Pass A: stream once; classify, store, collect in-window ----
    {
        const unsigned curaddr = (unsigned)__cvta_generic_to_shared(&s_cur);
        const unsigned valbase = (unsigned)__cvta_generic_to_shared(s_val);
        const unsigned idxbase = (unsigned)__cvta_generic_to_shared(s_idx);
        int chi = 0;
#pragma unroll
        for (int i = 0; i < 4; ++i) {
            float4 v = __ldg(&gp[i * TPB]);
            unsigned base = ((unsigned)(i * TPB + tid)) << 2;
            float4 o;
            o.x = classify_elem(v.x, base + 0, chi, curaddr, valbase, idxbase);
            o.y = classify_elem(v.y, base + 1, chi, curaddr, valbase, idxbase);
            o.z = classify_elem(v.z, base + 2, chi, curaddr, valbase, idxbase);
            o.w = classify_elem(v.w, base + 3, chi, curaddr, valbase, idxbase);
            qp[i * TPB] = o;
        }
        chi = __reduce_add_sync(0xFFFFFFFFu, chi);
        if (lane == 0) atomicAdd(&s_chi, chi);
    }
    __syncthreads();

    const int ncoll  = s_cur;
    const int chitot = s_chi;
    const int nscan  = (ncoll < MAXCOLL) ? ncoll : MAXCOLL;
    if (tid == 0 && ncoll > MAXCOLL) s_fb = 1;        // overflow -> fallback

    // ---- Pass B: histogram collected (~371) into 186 key-domain bins ----
    for (int i = tid; i < nscan; i += TPB) {
        unsigned u = s_val[i];
        atomicAdd(&s_hist[(UB - 1u - u) >> BIN_SHIFT], 1);
    }
    __syncthreads();

    // ---- Pass C: warp-0 suffix scan; bucket j* with cum(j*)>=k>cum(j*+1) ----
    if (tid < 32) {
        int h[6];
        int lt = 0;
#pragma unroll
        for (int r = 0; r < 6; ++r) { h[r] = s_hist[lane * 6 + r]; lt += h[r]; }
        int x = lt;                                   // suffix sum over lanes
#pragma unroll
        for (int d = 1; d < 32; d <<= 1) {
            int y = __shfl_down_sync(0xFFFFFFFFu, x, d);
            if (lane + d < 32) x += y;
        }
        const int cumbase = chitot + x;               // count(bin >= 6*lane)
        int cand = -1, candcum = 0, candh = 0, pre = 0;
#pragma unroll
        for (int r = 0; r < 6; ++r) {
            int j   = lane * 6 + r;
            int cum = cumbase - pre;                  // count(bin >= j)
            if (cum >= kth) { cand = j; candcum = cum; candh = h[r]; }
            pre += h[r];
        }
        int jstar = __reduce_max_sync(0xFFFFFFFFu, cand);
        if (cand == jstar && jstar >= 0) {            // unique owner lane
            s_j = jstar;
            s_m = kth - (candcum - candh);            // 1 <= m <= bucket size
            s_nb = candh;
            if (candh > MAXB) s_fb = 1;
        }
        if (lane == 0 && (jstar < 0 || chitot >= kth)) s_fb = 1;
    }
    __syncthreads();

    if (!s_fb) {
        // ---- Pass D: gather bucket members as UNIQUE packed keys ----
        // key = (~u) << 16 | idx : monotone in value, idx tiebreak, unique.
        const unsigned ubhi = UB - 1u - ((unsigned)s_j << BIN_SHIFT);
        for (int i = tid; i < nscan; i += TPB) {
            unsigned u = s_val[i];
            if ((ubhi - u) < (1u << BIN_SHIFT)) {
                int pos = atomicAdd(&s_cur2, 1);
                s_bucket[pos] = ((unsigned long long)(~u) << 16) | s_idx[i];
            }
        }
        __syncthreads();

        // warp 0: m-th largest among <=32 unique keys
        if (tid < 32) {
            const int nb = s_nb, m = s_m;
            unsigned long long kv = (lane < nb) ? s_bucket[lane] : 0ull;
            for (int i = 1; i < m; ++i) {
                unsigned long long mx = warp_max_u64(kv);
                kv = (kv == mx) ? 0ull : kv;          // unique: removes one
            }
            unsigned long long sel = warp_max_u64(kv);
            if (lane == 0)
                s_ft = __uint_as_float(~(unsigned)(sel >> 16));
        }
        __syncthreads();
        const float ft = s_ft;

        // ---- Pass D': overwrite kept in-window elements (scattered 4B) ----
        float* orow = (float*)(out + row_f4);
        for (int i = tid; i < nscan; i += TPB) {
            float f = __uint_as_float(s_val[i]);
            if (f >= ft) orow[s_idx[i]] = f;
        }
    } else {
        // ---- exact fallback: descent over cached global row, full rewrite ----
        unsigned result = 0u;
#pragma unroll 1
        for (int bit = 31; bit >= 0; --bit) {
            const unsigned t = result | (1u << bit);
            int c = 0;
#pragma unroll
            for (int i = 0; i < 4; ++i) {
                float4 v = __ldg(&gp[i * TPB]);
                c += (f2key(v.x) >= t) ? 1 : 0;
                c += (f2key(v.y) >= t) ? 1 : 0;
                c += (f2key(v.z) >= t) ? 1 : 0;
                c += (f2key(v.w) >= t) ? 1 : 0;
            }
            c = __reduce_add_sync(0xFFFFFFFFu, c);
            if (lane == 0) s_part[bit & 1][tid >> 5] = c;
            __syncthreads();
            int tot = 0;
#pragma unroll
            for (int w = 0; w < TPB / 32; ++w) tot += s_part[bit & 1][w];
            if (tot >= kth) { result = t; if (tot == kth) break; }   // uniform
        }
        const float ft = key2f(result);
#pragma unroll
        for (int i = 0; i < 4; ++i) {
            float4 v = __ldg(&gp[i * TPB]);
            v.x = (v.x >= ft) ? v.x : 0.0f;
            v.y = (v.y >= ft) ? v.y : 0.0f;
            v.z = (v.z >= ft) ? v.z : 0.0f;
            v.w = (v.w >= ft) ? v.w : 0.0f;
            qp[i * TPB] = v;
        }
    }
}

extern "C" void kernel_launch(void* const* d_in, const int* in_sizes, int n_in,
                              void* d_out, int out_size)
{
    const float4* in  = (const float4*)d_in[0];
    float4*       out = (float4*)d_out;

    const int rows = in_sizes[0] / N_COLS;        // 8 * 4096 = 32768

    int k = (int)((double)N_COLS * (1.0 - 0.3));  // 2867, matches Python int()
    if (k < 1) k = 1;

    topk_sparsify_kernel<<<rows, TPB>>>(in, out, k);
}